// round 2
// baseline (speedup 1.0000x reference)
#include <cuda_runtime.h>
#include <math.h>

#define BATCH 32768
#define SDIM 512
#define HID 256
#define ACT 8
#define HOR 10

// ---------------- scratch (device globals; no allocation) ----------------
__device__ float g_h1[BATCH * HID];
__device__ float g_h2[BATCH * HID];
__device__ float g_init[BATCH * 2 * HID];   // [0,B*H): h0, [B*H,2BH): h1
__device__ float g_h0b[BATCH * HID];
__device__ float g_h1b[BATCH * HID];
__device__ float g_a0[BATCH * ACT];
__device__ float g_a1[BATCH * ACT];

// ---------------- zero kernel ----------------
__global__ void k_zero(float* __restrict__ p, int n) {
    int i = blockIdx.x * blockDim.x + threadIdx.x;
    if (i < n) p[i] = 0.0f;
}

// ---------------- fc1 + LayerNorm + ReLU ----------------
// out[B,256] = relu(LN(concat(s0,s1) @ W1.T + b1))
// 32 rows per CTA, all 256 cols, K=1024
__global__ __launch_bounds__(256) void k_fc1_ln(
    const float* __restrict__ s0, const float* __restrict__ s1,
    const float* __restrict__ W1, const float* __restrict__ b1,
    const float* __restrict__ gam, const float* __restrict__ bet,
    float* __restrict__ out)
{
    __shared__ __align__(16) float As[32][33];
    __shared__ __align__(16) float Ws[32][260];   // [kk][n], padded

    const int tid = threadIdx.x;
    const int rowBase = blockIdx.x * 32;
    const int tg = tid >> 5;      // 0..7 -> rows tg*4..tg*4+3
    const int lane = tid & 31;    // cols lane*8..lane*8+7

    float acc[4][8];
#pragma unroll
    for (int i = 0; i < 4; i++)
#pragma unroll
        for (int j = 0; j < 8; j++) acc[i][j] = 0.0f;

    for (int k0 = 0; k0 < 1024; k0 += 32) {
#pragma unroll
        for (int i = 0; i < 4; i++) {
            int idx = i * 256 + tid;
            int r = idx >> 5, kk = idx & 31;
            int k = k0 + kk;
            As[r][kk] = (k < 512) ? s0[(rowBase + r) * 512 + k]
                                  : s1[(rowBase + r) * 512 + (k - 512)];
        }
#pragma unroll
        for (int i = 0; i < 32; i++) {
            int idx = i * 256 + tid;
            int n = idx >> 5, kk = idx & 31;
            Ws[kk][n] = W1[n * 1024 + k0 + kk];
        }
        __syncthreads();
#pragma unroll
        for (int kk = 0; kk < 32; kk++) {
            float a0 = As[tg * 4 + 0][kk];
            float a1 = As[tg * 4 + 1][kk];
            float a2 = As[tg * 4 + 2][kk];
            float a3 = As[tg * 4 + 3][kk];
            float4 w0 = *(const float4*)&Ws[kk][lane * 8];
            float4 w1 = *(const float4*)&Ws[kk][lane * 8 + 4];
            float w[8] = {w0.x, w0.y, w0.z, w0.w, w1.x, w1.y, w1.z, w1.w};
#pragma unroll
            for (int j = 0; j < 8; j++) {
                acc[0][j] += a0 * w[j];
                acc[1][j] += a1 * w[j];
                acc[2][j] += a2 * w[j];
                acc[3][j] += a3 * w[j];
            }
        }
        __syncthreads();
    }

    // stash tile for the row-wise LayerNorm reduction (reuse Ws storage)
    float* Cs = &Ws[0][0];
#pragma unroll
    for (int i = 0; i < 4; i++)
#pragma unroll
        for (int j = 0; j < 8; j++)
            Cs[(tg * 4 + i) * 260 + lane * 8 + j] = acc[i][j];
    __syncthreads();

    // warp tg reduces rows tg*4 .. tg*4+3
    for (int rr = 0; rr < 4; rr++) {
        int row = tg * 4 + rr;
        float v[8];
        float sum = 0.0f, sq = 0.0f;
#pragma unroll
        for (int i = 0; i < 8; i++) {
            int c = lane + 32 * i;
            v[i] = Cs[row * 260 + c] + b1[c];
            sum += v[i];
            sq += v[i] * v[i];
        }
#pragma unroll
        for (int o = 16; o; o >>= 1) {
            sum += __shfl_xor_sync(0xffffffffu, sum, o);
            sq  += __shfl_xor_sync(0xffffffffu, sq, o);
        }
        float mean = sum * (1.0f / 256.0f);
        float var  = sq * (1.0f / 256.0f) - mean * mean;
        float rstd = rsqrtf(var + 1e-5f);
#pragma unroll
        for (int i = 0; i < 8; i++) {
            int c = lane + 32 * i;
            float o = (v[i] - mean) * rstd * gam[c] + bet[c];
            out[(rowBase + row) * 256 + c] = fmaxf(o, 0.0f);
        }
    }
}

// ---------------- generic GEMM: C[M,N] = X[M,256] @ W[N,256].T + b (opt relu) ----------------
// BM=BN=128, BK=8, 256 threads, 8x8 per thread
template <int RELU>
__global__ __launch_bounds__(256) void k_gemm(
    const float* __restrict__ X, const float* __restrict__ W,
    const float* __restrict__ b, float* __restrict__ C, int N)
{
    __shared__ __align__(16) float Xs[8][132];
    __shared__ __align__(16) float Ws[8][132];

    const int tid = threadIdx.x;
    const int m0 = blockIdx.y * 128;
    const int n0 = blockIdx.x * 128;
    const int tx = tid & 15;   // cols tx*8..+7
    const int ty = tid >> 4;   // rows ty*8..+7

    float acc[8][8];
#pragma unroll
    for (int i = 0; i < 8; i++)
#pragma unroll
        for (int j = 0; j < 8; j++) acc[i][j] = 0.0f;

    for (int k0 = 0; k0 < 256; k0 += 8) {
#pragma unroll
        for (int i = 0; i < 4; i++) {
            int idx = i * 256 + tid;
            int r = idx >> 3, kk = idx & 7;
            Xs[kk][r] = X[(m0 + r) * 256 + k0 + kk];
            Ws[kk][r] = W[(n0 + r) * 256 + k0 + kk];
        }
        __syncthreads();
#pragma unroll
        for (int kk = 0; kk < 8; kk++) {
            float4 xa = *(const float4*)&Xs[kk][ty * 8];
            float4 xb = *(const float4*)&Xs[kk][ty * 8 + 4];
            float4 wa = *(const float4*)&Ws[kk][tx * 8];
            float4 wb = *(const float4*)&Ws[kk][tx * 8 + 4];
            float x[8] = {xa.x, xa.y, xa.z, xa.w, xb.x, xb.y, xb.z, xb.w};
            float w[8] = {wa.x, wa.y, wa.z, wa.w, wb.x, wb.y, wb.z, wb.w};
#pragma unroll
            for (int i = 0; i < 8; i++)
#pragma unroll
                for (int j = 0; j < 8; j++) acc[i][j] += x[i] * w[j];
        }
        __syncthreads();
    }

#pragma unroll
    for (int i = 0; i < 8; i++) {
        int row = m0 + ty * 8 + i;
#pragma unroll
        for (int j = 0; j < 8; j++) {
            int col = n0 + tx * 8 + j;
            float v = acc[i][j] + b[col];
            if (RELU) v = fmaxf(v, 0.0f);
            C[row * N + col] = v;
        }
    }
}

// ---------------- GRU cell 0: x = a [B,8] (K=8), h [B,256] ----------------
// h_out = (1-z)*n + z*h ; gates [r,z,n], n = tanh(i_n + r*h_n)
__global__ __launch_bounds__(256) void k_gru0(
    const float* __restrict__ a_in, const float* __restrict__ h_in,
    const float* __restrict__ Wih, const float* __restrict__ Whh,
    const float* __restrict__ bih, const float* __restrict__ bhh,
    float* __restrict__ h_out)
{
    __shared__ __align__(16) float as_s[64][9];
    __shared__ __align__(16) float wi_s[3][8][64];
    __shared__ __align__(16) float hs[8][68];
    __shared__ __align__(16) float wh_s[3][8][64];

    const int tid = threadIdx.x;
    const int m0 = blockIdx.y * 64;
    const int c0b = blockIdx.x * 64;
    const int tx = tid & 15, ty = tid >> 4;
    const int r0 = ty * 4, c0 = tx * 4;

    float accR[4][4], accZ[4][4], accN[4][4], accHN[4][4];
#pragma unroll
    for (int i = 0; i < 4; i++)
#pragma unroll
        for (int j = 0; j < 4; j++) {
            accR[i][j] = 0.0f; accZ[i][j] = 0.0f;
            accN[i][j] = 0.0f; accHN[i][j] = 0.0f;
        }

    // K=8 input path
#pragma unroll
    for (int i = 0; i < 2; i++) {
        int idx = i * 256 + tid;
        int r = idx >> 3, kk = idx & 7;
        as_s[r][kk] = a_in[(m0 + r) * 8 + kk];
    }
#pragma unroll
    for (int g = 0; g < 3; g++)
#pragma unroll
        for (int i = 0; i < 2; i++) {
            int idx = i * 256 + tid;
            int c = idx >> 3, kk = idx & 7;
            wi_s[g][kk][c] = Wih[(g * 256 + c0b + c) * 8 + kk];
        }
    __syncthreads();
#pragma unroll
    for (int kk = 0; kk < 8; kk++) {
        float xv[4];
#pragma unroll
        for (int i = 0; i < 4; i++) xv[i] = as_s[r0 + i][kk];
        float4 wr = *(const float4*)&wi_s[0][kk][c0];
        float4 wz = *(const float4*)&wi_s[1][kk][c0];
        float4 wn = *(const float4*)&wi_s[2][kk][c0];
        float wrv[4] = {wr.x, wr.y, wr.z, wr.w};
        float wzv[4] = {wz.x, wz.y, wz.z, wz.w};
        float wnv[4] = {wn.x, wn.y, wn.z, wn.w};
#pragma unroll
        for (int i = 0; i < 4; i++)
#pragma unroll
            for (int j = 0; j < 4; j++) {
                accR[i][j] += xv[i] * wrv[j];
                accZ[i][j] += xv[i] * wzv[j];
                accN[i][j] += xv[i] * wnv[j];
            }
    }

    // K=256 hidden path
    for (int k0 = 0; k0 < 256; k0 += 8) {
#pragma unroll
        for (int i = 0; i < 2; i++) {
            int idx = i * 256 + tid;
            int r = idx >> 3, kk = idx & 7;
            hs[kk][r] = h_in[(m0 + r) * 256 + k0 + kk];
        }
#pragma unroll
        for (int g = 0; g < 3; g++)
#pragma unroll
            for (int i = 0; i < 2; i++) {
                int idx = i * 256 + tid;
                int c = idx >> 3, kk = idx & 7;
                wh_s[g][kk][c] = Whh[(g * 256 + c0b + c) * 256 + k0 + kk];
            }
        __syncthreads();
#pragma unroll
        for (int kk = 0; kk < 8; kk++) {
            float hv[4];
#pragma unroll
            for (int i = 0; i < 4; i++) hv[i] = hs[kk][r0 + i];
            float4 wr = *(const float4*)&wh_s[0][kk][c0];
            float4 wz = *(const float4*)&wh_s[1][kk][c0];
            float4 wn = *(const float4*)&wh_s[2][kk][c0];
            float wrv[4] = {wr.x, wr.y, wr.z, wr.w};
            float wzv[4] = {wz.x, wz.y, wz.z, wz.w};
            float wnv[4] = {wn.x, wn.y, wn.z, wn.w};
#pragma unroll
            for (int i = 0; i < 4; i++)
#pragma unroll
                for (int j = 0; j < 4; j++) {
                    accR[i][j]  += hv[i] * wrv[j];
                    accZ[i][j]  += hv[i] * wzv[j];
                    accHN[i][j] += hv[i] * wnv[j];
                }
        }
        __syncthreads();
    }

#pragma unroll
    for (int i = 0; i < 4; i++) {
        int row = m0 + r0 + i;
#pragma unroll
        for (int j = 0; j < 4; j++) {
            int col = c0b + c0 + j;
            float r = 1.0f / (1.0f + expf(-(accR[i][j] + bih[col] + bhh[col])));
            float z = 1.0f / (1.0f + expf(-(accZ[i][j] + bih[col + 256] + bhh[col + 256])));
            float n = tanhf(accN[i][j] + bih[col + 512] + r * (accHN[i][j] + bhh[col + 512]));
            float hold = h_in[row * 256 + col];
            h_out[row * 256 + col] = (1.0f - z) * n + z * hold;
        }
    }
}

// ---------------- GRU cell 1: x [B,256], h [B,256] ----------------
__global__ __launch_bounds__(256) void k_gru1(
    const float* __restrict__ x_in, const float* __restrict__ h_in,
    const float* __restrict__ Wih, const float* __restrict__ Whh,
    const float* __restrict__ bih, const float* __restrict__ bhh,
    float* __restrict__ h_out)
{
    __shared__ __align__(16) float xs[8][68];
    __shared__ __align__(16) float hs[8][68];
    __shared__ __align__(16) float wi_s[3][8][64];
    __shared__ __align__(16) float wh_s[3][8][64];

    const int tid = threadIdx.x;
    const int m0 = blockIdx.y * 64;
    const int c0b = blockIdx.x * 64;
    const int tx = tid & 15, ty = tid >> 4;
    const int r0 = ty * 4, c0 = tx * 4;

    float accR[4][4], accZ[4][4], accN[4][4], accHN[4][4];
#pragma unroll
    for (int i = 0; i < 4; i++)
#pragma unroll
        for (int j = 0; j < 4; j++) {
            accR[i][j] = 0.0f; accZ[i][j] = 0.0f;
            accN[i][j] = 0.0f; accHN[i][j] = 0.0f;
        }

    for (int k0 = 0; k0 < 256; k0 += 8) {
#pragma unroll
        for (int i = 0; i < 2; i++) {
            int idx = i * 256 + tid;
            int r = idx >> 3, kk = idx & 7;
            xs[kk][r] = x_in[(m0 + r) * 256 + k0 + kk];
            hs[kk][r] = h_in[(m0 + r) * 256 + k0 + kk];
        }
#pragma unroll
        for (int g = 0; g < 3; g++)
#pragma unroll
            for (int i = 0; i < 2; i++) {
                int idx = i * 256 + tid;
                int c = idx >> 3, kk = idx & 7;
                wi_s[g][kk][c] = Wih[(g * 256 + c0b + c) * 256 + k0 + kk];
                wh_s[g][kk][c] = Whh[(g * 256 + c0b + c) * 256 + k0 + kk];
            }
        __syncthreads();
#pragma unroll
        for (int kk = 0; kk < 8; kk++) {
            float xv[4], hv[4];
#pragma unroll
            for (int i = 0; i < 4; i++) {
                xv[i] = xs[kk][r0 + i];
                hv[i] = hs[kk][r0 + i];
            }
            float4 ir = *(const float4*)&wi_s[0][kk][c0];
            float4 iz = *(const float4*)&wi_s[1][kk][c0];
            float4 in_ = *(const float4*)&wi_s[2][kk][c0];
            float4 hr = *(const float4*)&wh_s[0][kk][c0];
            float4 hz = *(const float4*)&wh_s[1][kk][c0];
            float4 hn = *(const float4*)&wh_s[2][kk][c0];
            float irv[4] = {ir.x, ir.y, ir.z, ir.w};
            float izv[4] = {iz.x, iz.y, iz.z, iz.w};
            float inv[4] = {in_.x, in_.y, in_.z, in_.w};
            float hrv[4] = {hr.x, hr.y, hr.z, hr.w};
            float hzv[4] = {hz.x, hz.y, hz.z, hz.w};
            float hnv[4] = {hn.x, hn.y, hn.z, hn.w};
#pragma unroll
            for (int i = 0; i < 4; i++)
#pragma unroll
                for (int j = 0; j < 4; j++) {
                    accR[i][j]  += xv[i] * irv[j];
                    accR[i][j]  += hv[i] * hrv[j];
                    accZ[i][j]  += xv[i] * izv[j];
                    accZ[i][j]  += hv[i] * hzv[j];
                    accN[i][j]  += xv[i] * inv[j];
                    accHN[i][j] += hv[i] * hnv[j];
                }
        }
        __syncthreads();
    }

#pragma unroll
    for (int i = 0; i < 4; i++) {
        int row = m0 + r0 + i;
#pragma unroll
        for (int j = 0; j < 4; j++) {
            int col = c0b + c0 + j;
            float r = 1.0f / (1.0f + expf(-(accR[i][j] + bih[col] + bhh[col])));
            float z = 1.0f / (1.0f + expf(-(accZ[i][j] + bih[col + 256] + bhh[col + 256])));
            float n = tanhf(accN[i][j] + bih[col + 512] + r * (accHN[i][j] + bhh[col + 512]));
            float hold = h_in[row * 256 + col];
            h_out[row * 256 + col] = (1.0f - z) * n + z * hold;
        }
    }
}

// ---------------- logits + softmax ----------------
// logits[b,t,:] = h1n[b] @ Wa.T + ba ; a_next = softmax(logits)
__global__ __launch_bounds__(256) void k_logits(
    const float* __restrict__ h, const float* __restrict__ Wa,
    const float* __restrict__ ba, float* __restrict__ out,
    float* __restrict__ a_next, int t)
{
    __shared__ float hs[32][257];
    __shared__ float Was[8][257];

    const int tid = threadIdx.x;
    const int rb0 = blockIdx.x * 32;

#pragma unroll
    for (int i = 0; i < 8; i++) {
        int idx = i * 256 + tid;
        int j = idx >> 8, k = idx & 255;
        Was[j][k] = Wa[j * 256 + k];
    }
#pragma unroll
    for (int i = 0; i < 32; i++) {
        int idx = i * 256 + tid;
        int r = idx >> 8, k = idx & 255;
        hs[r][k] = h[(rb0 + r) * 256 + k];
    }
    __syncthreads();

    const int r = tid >> 3, j = tid & 7;
    float s0 = 0.0f, s1 = 0.0f, s2 = 0.0f, s3 = 0.0f;
#pragma unroll 8
    for (int k = 0; k < 256; k += 4) {
        s0 += hs[r][k + 0] * Was[j][k + 0];
        s1 += hs[r][k + 1] * Was[j][k + 1];
        s2 += hs[r][k + 2] * Was[j][k + 2];
        s3 += hs[r][k + 3] * Was[j][k + 3];
    }
    float acc = (s0 + s1) + (s2 + s3) + ba[j];

    out[(rb0 + r) * (HOR * ACT) + t * ACT + j] = acc;

    // softmax within the 8-lane group (xor 1,2,4 stays inside the group)
    float m = acc;
#pragma unroll
    for (int o = 4; o; o >>= 1) m = fmaxf(m, __shfl_xor_sync(0xffffffffu, m, o));
    float e = expf(acc - m);
    float s = e;
#pragma unroll
    for (int o = 4; o; o >>= 1) s += __shfl_xor_sync(0xffffffffu, s, o);
    a_next[(rb0 + r) * ACT + j] = e / s;
}

// ---------------- host ----------------
extern "C" void kernel_launch(void* const* d_in, const int* in_sizes, int n_in,
                              void* d_out, int out_size)
{
    const float* s0    = (const float*)d_in[0];
    const float* s1    = (const float*)d_in[1];
    // d_in[2] = horizon (int32) — fixed at 10, unused
    const float* W1    = (const float*)d_in[3];
    const float* b1    = (const float*)d_in[4];
    const float* lng   = (const float*)d_in[5];
    const float* lnb   = (const float*)d_in[6];
    const float* W2    = (const float*)d_in[7];
    const float* b2    = (const float*)d_in[8];
    const float* Wih0  = (const float*)d_in[9];
    const float* Whh0  = (const float*)d_in[10];
    const float* bih0  = (const float*)d_in[11];
    const float* bhh0  = (const float*)d_in[12];
    const float* Wih1  = (const float*)d_in[13];
    const float* Whh1  = (const float*)d_in[14];
    const float* bih1  = (const float*)d_in[15];
    const float* bhh1  = (const float*)d_in[16];
    const float* Wa    = (const float*)d_in[17];
    const float* ba    = (const float*)d_in[18];
    const float* Winit = (const float*)d_in[19];
    const float* binit = (const float*)d_in[20];
    float* out = (float*)d_out;

    float *h1buf, *h2buf, *initbuf, *h0b, *h1b, *a0, *a1;
    cudaGetSymbolAddress((void**)&h1buf, g_h1);
    cudaGetSymbolAddress((void**)&h2buf, g_h2);
    cudaGetSymbolAddress((void**)&initbuf, g_init);
    cudaGetSymbolAddress((void**)&h0b, g_h0b);
    cudaGetSymbolAddress((void**)&h1b, g_h1b);
    cudaGetSymbolAddress((void**)&a0, g_a0);
    cudaGetSymbolAddress((void**)&a1, g_a1);

    // a0 = zeros (every replay)
    k_zero<<<(BATCH * ACT + 255) / 256, 256>>>(a0, BATCH * ACT);

    // prologue MLP
    k_fc1_ln<<<BATCH / 32, 256>>>(s0, s1, W1, b1, lng, lnb, h1buf);
    k_gemm<1><<<dim3(2, BATCH / 128), 256>>>(h1buf, W2, b2, h2buf, 256);
    k_gemm<0><<<dim3(4, BATCH / 128), 256>>>(h2buf, Winit, binit, initbuf, 512);

    float* h0bufs[2] = {initbuf, h0b};
    float* h1bufs[2] = {initbuf + BATCH * HID, h1b};
    float* abufs[2]  = {a0, a1};

    for (int t = 0; t < HOR; t++) {
        int cur = t & 1, nxt = 1 - cur;
        k_gru0<<<dim3(4, BATCH / 64), 256>>>(abufs[cur], h0bufs[cur],
                                             Wih0, Whh0, bih0, bhh0, h0bufs[nxt]);
        k_gru1<<<dim3(4, BATCH / 64), 256>>>(h0bufs[nxt], h1bufs[cur],
                                             Wih1, Whh1, bih1, bhh1, h1bufs[nxt]);
        k_logits<<<BATCH / 32, 256>>>(h1bufs[nxt], Wa, ba, out, abufs[nxt], t);
    }
}

// round 3
// speedup vs baseline: 2.4804x; 2.4804x over previous
#include <cuda_runtime.h>
#include <math.h>
#include <stdint.h>

#define BATCH 32768
#define SDIM 512
#define HID 256
#define ACT 8
#define HOR 10

// ---------------- scratch (device globals; no allocation) ----------------
__device__ float g_h1[BATCH * HID];
__device__ float g_h2[BATCH * HID];
__device__ float g_init[BATCH * 2 * HID];   // [0,B*H): h0, [B*H,2BH): h1
__device__ float g_h0b[BATCH * HID];
__device__ float g_h1b[BATCH * HID];
__device__ float g_a0[BATCH * ACT];
__device__ float g_a1[BATCH * ACT];

// ---------------- helpers ----------------
__device__ __forceinline__ uint32_t f2tf(float f) {
    uint32_t u;
    asm("cvt.rna.tf32.f32 %0, %1;" : "=r"(u) : "f"(f));
    return u;
}

__device__ __forceinline__ void mma8(float c[4], const uint32_t a[4],
                                     uint32_t b0, uint32_t b1) {
    asm volatile(
        "mma.sync.aligned.m16n8k8.row.col.f32.tf32.tf32.f32 "
        "{%0,%1,%2,%3}, {%4,%5,%6,%7}, {%8,%9}, {%0,%1,%2,%3};"
        : "+f"(c[0]), "+f"(c[1]), "+f"(c[2]), "+f"(c[3])
        : "r"(a[0]), "r"(a[1]), "r"(a[2]), "r"(a[3]), "r"(b0), "r"(b1));
}

__device__ __forceinline__ float sigm(float x) {
    return 1.0f / (1.0f + expf(-x));
}

// ---------------- zero kernel ----------------
__global__ void k_zero(float* __restrict__ p, int n) {
    int i = blockIdx.x * blockDim.x + threadIdx.x;
    if (i < n) p[i] = 0.0f;
}

// ---------------- fc1 (tf32 MMA) + LayerNorm + ReLU ----------------
// out[B,256] = relu(LN(concat(s0,s1) @ W1.T + b1)); BM=32, BN=256, K=1024
__global__ __launch_bounds__(256) void k_fc1_mma(
    const float* __restrict__ s0, const float* __restrict__ s1,
    const float* __restrict__ W1, const float* __restrict__ b1,
    const float* __restrict__ gam, const float* __restrict__ bet,
    float* __restrict__ out)
{
    // SB partitions: Xs[32][20] at 0, Ws[256][20] at 640; epilogue Cs[32][264] floats
    __shared__ __align__(16) uint32_t SB[8448];

    const int tid  = threadIdx.x;
    const int rowBase = blockIdx.x * 32;
    const int warp = tid >> 5, lane = tid & 31;
    const int wm = warp >> 2, wn = warp & 3;       // 2m x 4n
    const int g  = lane >> 2, t4 = lane & 3;

    float acc[8][4];
#pragma unroll
    for (int i = 0; i < 8; i++)
#pragma unroll
        for (int j = 0; j < 4; j++) acc[i][j] = 0.0f;

    for (int k0 = 0; k0 < 1024; k0 += 16) {
        // load X tile (32x16): threads 0..127
        if (tid < 128) {
            int r = tid >> 2, lk = (tid & 3) * 4;
            int k = k0 + lk;
            float4 v;
            if (k < 512) v = *(const float4*)&s0[(rowBase + r) * 512 + k];
            else         v = *(const float4*)&s1[(rowBase + r) * 512 + (k - 512)];
            uint32_t* Xp = &SB[r * 20 + lk];
            Xp[0] = f2tf(v.x); Xp[1] = f2tf(v.y); Xp[2] = f2tf(v.z); Xp[3] = f2tf(v.w);
        }
        // load W tile (256x16): 1024 float4, 4 per thread
#pragma unroll
        for (int i = 0; i < 4; i++) {
            int idx = i * 256 + tid;
            int c = idx >> 2, lk = (idx & 3) * 4;
            float4 v = *(const float4*)&W1[c * 1024 + k0 + lk];
            uint32_t* Wp = &SB[640 + c * 20 + lk];
            Wp[0] = f2tf(v.x); Wp[1] = f2tf(v.y); Wp[2] = f2tf(v.z); Wp[3] = f2tf(v.w);
        }
        __syncthreads();
#pragma unroll
        for (int ks = 0; ks < 16; ks += 8) {
            uint32_t a[4];
            a[0] = SB[(wm * 16 + g) * 20 + ks + t4];
            a[1] = SB[(wm * 16 + g + 8) * 20 + ks + t4];
            a[2] = SB[(wm * 16 + g) * 20 + ks + t4 + 4];
            a[3] = SB[(wm * 16 + g + 8) * 20 + ks + t4 + 4];
#pragma unroll
            for (int nt = 0; nt < 8; nt++) {
                int c = wn * 64 + nt * 8 + g;
                uint32_t b0 = SB[640 + c * 20 + ks + t4];
                uint32_t b1 = SB[640 + c * 20 + ks + t4 + 4];
                mma8(acc[nt], a, b0, b1);
            }
        }
        __syncthreads();
    }

    // stash fragments into Cs[32][264]
    float* Cs = (float*)SB;
#pragma unroll
    for (int nt = 0; nt < 8; nt++)
#pragma unroll
        for (int rix = 0; rix < 4; rix++) {
            int row = wm * 16 + g + 8 * (rix >> 1);
            int col = wn * 64 + nt * 8 + t4 * 2 + (rix & 1);
            Cs[row * 264 + col] = acc[nt][rix];
        }
    __syncthreads();

    // LayerNorm: warp handles rows warp*4 .. warp*4+3
    for (int rr = 0; rr < 4; rr++) {
        int row = warp * 4 + rr;
        float v[8];
        float sum = 0.0f, sq = 0.0f;
#pragma unroll
        for (int i = 0; i < 8; i++) {
            int c = lane + 32 * i;
            v[i] = Cs[row * 264 + c] + b1[c];
            sum += v[i];
            sq  += v[i] * v[i];
        }
#pragma unroll
        for (int o = 16; o; o >>= 1) {
            sum += __shfl_xor_sync(0xffffffffu, sum, o);
            sq  += __shfl_xor_sync(0xffffffffu, sq, o);
        }
        float mean = sum * (1.0f / 256.0f);
        float var  = sq * (1.0f / 256.0f) - mean * mean;
        float rstd = rsqrtf(var + 1e-5f);
#pragma unroll
        for (int i = 0; i < 8; i++) {
            int c = lane + 32 * i;
            float o = (v[i] - mean) * rstd * gam[c] + bet[c];
            out[(rowBase + row) * 256 + c] = fmaxf(o, 0.0f);
        }
    }
}

// ---------------- generic tf32 MMA GEMM: C[M,N] = X[M,256] @ W[N,256].T + b ----------------
// BM=64, BN=64, BK=16; 8 warps (4m x 2n)
template <int RELU>
__global__ __launch_bounds__(256) void k_gemm_mma(
    const float* __restrict__ X, const float* __restrict__ W,
    const float* __restrict__ b, float* __restrict__ C, int N)
{
    __shared__ __align__(16) uint32_t Xs[64][20];
    __shared__ __align__(16) uint32_t Ws[64][20];

    const int tid = threadIdx.x;
    const int m0 = blockIdx.y * 64, n0 = blockIdx.x * 64;
    const int warp = tid >> 5, lane = tid & 31;
    const int wm = warp >> 1, wn = warp & 1;
    const int g = lane >> 2, t4 = lane & 3;
    const int lr = tid >> 2, lk = (tid & 3) * 4;

    float acc[4][4];
#pragma unroll
    for (int i = 0; i < 4; i++)
#pragma unroll
        for (int j = 0; j < 4; j++) acc[i][j] = 0.0f;

    for (int k0 = 0; k0 < 256; k0 += 16) {
        float4 xv = *(const float4*)&X[(m0 + lr) * 256 + k0 + lk];
        float4 wv = *(const float4*)&W[(n0 + lr) * 256 + k0 + lk];
        Xs[lr][lk + 0] = f2tf(xv.x); Xs[lr][lk + 1] = f2tf(xv.y);
        Xs[lr][lk + 2] = f2tf(xv.z); Xs[lr][lk + 3] = f2tf(xv.w);
        Ws[lr][lk + 0] = f2tf(wv.x); Ws[lr][lk + 1] = f2tf(wv.y);
        Ws[lr][lk + 2] = f2tf(wv.z); Ws[lr][lk + 3] = f2tf(wv.w);
        __syncthreads();
#pragma unroll
        for (int ks = 0; ks < 16; ks += 8) {
            uint32_t a[4];
            a[0] = Xs[wm * 16 + g][ks + t4];
            a[1] = Xs[wm * 16 + g + 8][ks + t4];
            a[2] = Xs[wm * 16 + g][ks + t4 + 4];
            a[3] = Xs[wm * 16 + g + 8][ks + t4 + 4];
#pragma unroll
            for (int nt = 0; nt < 4; nt++) {
                int c = wn * 32 + nt * 8 + g;
                mma8(acc[nt], a, Ws[c][ks + t4], Ws[c][ks + t4 + 4]);
            }
        }
        __syncthreads();
    }

#pragma unroll
    for (int nt = 0; nt < 4; nt++)
#pragma unroll
        for (int rix = 0; rix < 4; rix++) {
            int row = m0 + wm * 16 + g + 8 * (rix >> 1);
            int col = n0 + wn * 32 + nt * 8 + t4 * 2 + (rix & 1);
            float v = acc[nt][rix] + b[col];
            if (RELU) v = fmaxf(v, 0.0f);
            C[row * N + col] = v;
        }
}

// ---------------- GRU cell 1 (tf32 MMA): x [B,256], h [B,256] ----------------
// accR = x@Wir + h@Whr ; accZ = x@Wiz + h@Whz ; accIN = x@Win ; accHN = h@Whn
__global__ __launch_bounds__(256) void k_gru1_mma(
    const float* __restrict__ x_in, const float* __restrict__ h_in,
    const float* __restrict__ Wih, const float* __restrict__ Whh,
    const float* __restrict__ bih, const float* __restrict__ bhh,
    float* __restrict__ h_out)
{
    __shared__ __align__(16) uint32_t Xs[64][20];
    __shared__ __align__(16) uint32_t Hs[64][20];
    __shared__ __align__(16) uint32_t Ws[6][64][20]; // ir,iz,in,hr,hz,hn

    const int tid = threadIdx.x;
    const int m0 = blockIdx.y * 64, c0b = blockIdx.x * 64;
    const int warp = tid >> 5, lane = tid & 31;
    const int wm = warp >> 1, wn = warp & 1;
    const int g = lane >> 2, t4 = lane & 3;
    const int lr = tid >> 2, lk = (tid & 3) * 4;

    float accR[4][4], accZ[4][4], accIN[4][4], accHN[4][4];
#pragma unroll
    for (int i = 0; i < 4; i++)
#pragma unroll
        for (int j = 0; j < 4; j++) {
            accR[i][j] = 0.0f; accZ[i][j] = 0.0f;
            accIN[i][j] = 0.0f; accHN[i][j] = 0.0f;
        }

    for (int k0 = 0; k0 < 256; k0 += 16) {
        float4 xv = *(const float4*)&x_in[(m0 + lr) * 256 + k0 + lk];
        float4 hv = *(const float4*)&h_in[(m0 + lr) * 256 + k0 + lk];
        Xs[lr][lk + 0] = f2tf(xv.x); Xs[lr][lk + 1] = f2tf(xv.y);
        Xs[lr][lk + 2] = f2tf(xv.z); Xs[lr][lk + 3] = f2tf(xv.w);
        Hs[lr][lk + 0] = f2tf(hv.x); Hs[lr][lk + 1] = f2tf(hv.y);
        Hs[lr][lk + 2] = f2tf(hv.z); Hs[lr][lk + 3] = f2tf(hv.w);
#pragma unroll
        for (int gg = 0; gg < 6; gg++) {
            const float* Wsrc = (gg < 3) ? Wih : Whh;
            int grow = (gg % 3) * 256 + c0b + lr;
            float4 wv = *(const float4*)&Wsrc[grow * 256 + k0 + lk];
            Ws[gg][lr][lk + 0] = f2tf(wv.x); Ws[gg][lr][lk + 1] = f2tf(wv.y);
            Ws[gg][lr][lk + 2] = f2tf(wv.z); Ws[gg][lr][lk + 3] = f2tf(wv.w);
        }
        __syncthreads();
#pragma unroll
        for (int ks = 0; ks < 16; ks += 8) {
            uint32_t ax[4], ah[4];
            ax[0] = Xs[wm * 16 + g][ks + t4];
            ax[1] = Xs[wm * 16 + g + 8][ks + t4];
            ax[2] = Xs[wm * 16 + g][ks + t4 + 4];
            ax[3] = Xs[wm * 16 + g + 8][ks + t4 + 4];
            ah[0] = Hs[wm * 16 + g][ks + t4];
            ah[1] = Hs[wm * 16 + g + 8][ks + t4];
            ah[2] = Hs[wm * 16 + g][ks + t4 + 4];
            ah[3] = Hs[wm * 16 + g + 8][ks + t4 + 4];
#pragma unroll
            for (int nt = 0; nt < 4; nt++) {
                int c = wn * 32 + nt * 8 + g;
                mma8(accR[nt],  ax, Ws[0][c][ks + t4], Ws[0][c][ks + t4 + 4]);
                mma8(accR[nt],  ah, Ws[3][c][ks + t4], Ws[3][c][ks + t4 + 4]);
                mma8(accZ[nt],  ax, Ws[1][c][ks + t4], Ws[1][c][ks + t4 + 4]);
                mma8(accZ[nt],  ah, Ws[4][c][ks + t4], Ws[4][c][ks + t4 + 4]);
                mma8(accIN[nt], ax, Ws[2][c][ks + t4], Ws[2][c][ks + t4 + 4]);
                mma8(accHN[nt], ah, Ws[5][c][ks + t4], Ws[5][c][ks + t4 + 4]);
            }
        }
        __syncthreads();
    }

#pragma unroll
    for (int nt = 0; nt < 4; nt++)
#pragma unroll
        for (int rix = 0; rix < 4; rix++) {
            int row = m0 + wm * 16 + g + 8 * (rix >> 1);
            int col = c0b + wn * 32 + nt * 8 + t4 * 2 + (rix & 1);
            float r = sigm(accR[nt][rix] + bih[col] + bhh[col]);
            float z = sigm(accZ[nt][rix] + bih[col + 256] + bhh[col + 256]);
            float n = tanhf(accIN[nt][rix] + bih[col + 512] +
                            r * (accHN[nt][rix] + bhh[col + 512]));
            float hold = h_in[row * 256 + col];
            h_out[row * 256 + col] = (1.0f - z) * n + z * hold;
        }
}

// ---------------- GRU cell 0 (tf32 MMA): x = a [B,8] (K=8), h [B,256] ----------------
__global__ __launch_bounds__(256) void k_gru0_mma(
    const float* __restrict__ a_in, const float* __restrict__ h_in,
    const float* __restrict__ Wih, const float* __restrict__ Whh,
    const float* __restrict__ bih, const float* __restrict__ bhh,
    float* __restrict__ h_out)
{
    __shared__ __align__(16) uint32_t Hs[64][20];
    __shared__ __align__(16) uint32_t Ws[3][64][20];  // hr,hz,hn
    __shared__ __align__(16) uint32_t As[64][12];
    __shared__ __align__(16) uint32_t Wi0[3][64][12]; // ir,iz,in (K=8)

    const int tid = threadIdx.x;
    const int m0 = blockIdx.y * 64, c0b = blockIdx.x * 64;
    const int warp = tid >> 5, lane = tid & 31;
    const int wm = warp >> 1, wn = warp & 1;
    const int g = lane >> 2, t4 = lane & 3;
    const int lr = tid >> 2, lk = (tid & 3) * 4;

    float accR[4][4], accZ[4][4], accIN[4][4], accHN[4][4];
#pragma unroll
    for (int i = 0; i < 4; i++)
#pragma unroll
        for (int j = 0; j < 4; j++) {
            accR[i][j] = 0.0f; accZ[i][j] = 0.0f;
            accIN[i][j] = 0.0f; accHN[i][j] = 0.0f;
        }

    // --- x path: single k8 ---
    {
        int r = tid >> 2, k2 = (tid & 3) * 2;
        float2 av = *(const float2*)&a_in[(m0 + r) * 8 + k2];
        As[r][k2] = f2tf(av.x); As[r][k2 + 1] = f2tf(av.y);
#pragma unroll
        for (int gg = 0; gg < 3; gg++) {
            float2 wv = *(const float2*)&Wih[(gg * 256 + c0b + r) * 8 + k2];
            Wi0[gg][r][k2] = f2tf(wv.x); Wi0[gg][r][k2 + 1] = f2tf(wv.y);
        }
    }
    __syncthreads();
    {
        uint32_t a[4];
        a[0] = As[wm * 16 + g][t4];
        a[1] = As[wm * 16 + g + 8][t4];
        a[2] = As[wm * 16 + g][t4 + 4];
        a[3] = As[wm * 16 + g + 8][t4 + 4];
#pragma unroll
        for (int nt = 0; nt < 4; nt++) {
            int c = wn * 32 + nt * 8 + g;
            mma8(accR[nt],  a, Wi0[0][c][t4], Wi0[0][c][t4 + 4]);
            mma8(accZ[nt],  a, Wi0[1][c][t4], Wi0[1][c][t4 + 4]);
            mma8(accIN[nt], a, Wi0[2][c][t4], Wi0[2][c][t4 + 4]);
        }
    }

    // --- h path: K=256 ---
    for (int k0 = 0; k0 < 256; k0 += 16) {
        float4 hv = *(const float4*)&h_in[(m0 + lr) * 256 + k0 + lk];
        Hs[lr][lk + 0] = f2tf(hv.x); Hs[lr][lk + 1] = f2tf(hv.y);
        Hs[lr][lk + 2] = f2tf(hv.z); Hs[lr][lk + 3] = f2tf(hv.w);
#pragma unroll
        for (int gg = 0; gg < 3; gg++) {
            float4 wv = *(const float4*)&Whh[(gg * 256 + c0b + lr) * 256 + k0 + lk];
            Ws[gg][lr][lk + 0] = f2tf(wv.x); Ws[gg][lr][lk + 1] = f2tf(wv.y);
            Ws[gg][lr][lk + 2] = f2tf(wv.z); Ws[gg][lr][lk + 3] = f2tf(wv.w);
        }
        __syncthreads();
#pragma unroll
        for (int ks = 0; ks < 16; ks += 8) {
            uint32_t ah[4];
            ah[0] = Hs[wm * 16 + g][ks + t4];
            ah[1] = Hs[wm * 16 + g + 8][ks + t4];
            ah[2] = Hs[wm * 16 + g][ks + t4 + 4];
            ah[3] = Hs[wm * 16 + g + 8][ks + t4 + 4];
#pragma unroll
            for (int nt = 0; nt < 4; nt++) {
                int c = wn * 32 + nt * 8 + g;
                mma8(accR[nt],  ah, Ws[0][c][ks + t4], Ws[0][c][ks + t4 + 4]);
                mma8(accZ[nt],  ah, Ws[1][c][ks + t4], Ws[1][c][ks + t4 + 4]);
                mma8(accHN[nt], ah, Ws[2][c][ks + t4], Ws[2][c][ks + t4 + 4]);
            }
        }
        __syncthreads();
    }

#pragma unroll
    for (int nt = 0; nt < 4; nt++)
#pragma unroll
        for (int rix = 0; rix < 4; rix++) {
            int row = m0 + wm * 16 + g + 8 * (rix >> 1);
            int col = c0b + wn * 32 + nt * 8 + t4 * 2 + (rix & 1);
            float r = sigm(accR[nt][rix] + bih[col] + bhh[col]);
            float z = sigm(accZ[nt][rix] + bih[col + 256] + bhh[col + 256]);
            float n = tanhf(accIN[nt][rix] + bih[col + 512] +
                            r * (accHN[nt][rix] + bhh[col + 512]));
            float hold = h_in[row * 256 + col];
            h_out[row * 256 + col] = (1.0f - z) * n + z * hold;
        }
}

// ---------------- logits + softmax ----------------
__global__ __launch_bounds__(256) void k_logits(
    const float* __restrict__ h, const float* __restrict__ Wa,
    const float* __restrict__ ba, float* __restrict__ out,
    float* __restrict__ a_next, int t)
{
    __shared__ float hs[32][257];
    __shared__ float Was[8][257];

    const int tid = threadIdx.x;
    const int rb0 = blockIdx.x * 32;

#pragma unroll
    for (int i = 0; i < 8; i++) {
        int idx = i * 256 + tid;
        int j = idx >> 8, k = idx & 255;
        Was[j][k] = Wa[j * 256 + k];
    }
#pragma unroll
    for (int i = 0; i < 32; i++) {
        int idx = i * 256 + tid;
        int r = idx >> 8, k = idx & 255;
        hs[r][k] = h[(rb0 + r) * 256 + k];
    }
    __syncthreads();

    const int r = tid >> 3, j = tid & 7;
    float s0 = 0.0f, s1 = 0.0f, s2 = 0.0f, s3 = 0.0f;
#pragma unroll 8
    for (int k = 0; k < 256; k += 4) {
        s0 += hs[r][k + 0] * Was[j][k + 0];
        s1 += hs[r][k + 1] * Was[j][k + 1];
        s2 += hs[r][k + 2] * Was[j][k + 2];
        s3 += hs[r][k + 3] * Was[j][k + 3];
    }
    float acc = (s0 + s1) + (s2 + s3) + ba[j];

    out[(rb0 + r) * (HOR * ACT) + t * ACT + j] = acc;

    float m = acc;
#pragma unroll
    for (int o = 4; o; o >>= 1) m = fmaxf(m, __shfl_xor_sync(0xffffffffu, m, o));
    float e = expf(acc - m);
    float s = e;
#pragma unroll
    for (int o = 4; o; o >>= 1) s += __shfl_xor_sync(0xffffffffu, s, o);
    a_next[(rb0 + r) * ACT + j] = e / s;
}

// ---------------- host ----------------
extern "C" void kernel_launch(void* const* d_in, const int* in_sizes, int n_in,
                              void* d_out, int out_size)
{
    const float* s0    = (const float*)d_in[0];
    const float* s1    = (const float*)d_in[1];
    const float* W1    = (const float*)d_in[3];
    const float* b1    = (const float*)d_in[4];
    const float* lng   = (const float*)d_in[5];
    const float* lnb   = (const float*)d_in[6];
    const float* W2    = (const float*)d_in[7];
    const float* b2    = (const float*)d_in[8];
    const float* Wih0  = (const float*)d_in[9];
    const float* Whh0  = (const float*)d_in[10];
    const float* bih0  = (const float*)d_in[11];
    const float* bhh0  = (const float*)d_in[12];
    const float* Wih1  = (const float*)d_in[13];
    const float* Whh1  = (const float*)d_in[14];
    const float* bih1  = (const float*)d_in[15];
    const float* bhh1  = (const float*)d_in[16];
    const float* Wa    = (const float*)d_in[17];
    const float* ba    = (const float*)d_in[18];
    const float* Winit = (const float*)d_in[19];
    const float* binit = (const float*)d_in[20];
    float* out = (float*)d_out;

    float *h1buf, *h2buf, *initbuf, *h0b, *h1b, *a0, *a1;
    cudaGetSymbolAddress((void**)&h1buf, g_h1);
    cudaGetSymbolAddress((void**)&h2buf, g_h2);
    cudaGetSymbolAddress((void**)&initbuf, g_init);
    cudaGetSymbolAddress((void**)&h0b, g_h0b);
    cudaGetSymbolAddress((void**)&h1b, g_h1b);
    cudaGetSymbolAddress((void**)&a0, g_a0);
    cudaGetSymbolAddress((void**)&a1, g_a1);

    k_zero<<<(BATCH * ACT + 255) / 256, 256>>>(a0, BATCH * ACT);

    // prologue MLP
    k_fc1_mma<<<BATCH / 32, 256>>>(s0, s1, W1, b1, lng, lnb, h1buf);
    k_gemm_mma<1><<<dim3(4, BATCH / 64), 256>>>(h1buf, W2, b2, h2buf, 256);
    k_gemm_mma<0><<<dim3(8, BATCH / 64), 256>>>(h2buf, Winit, binit, initbuf, 512);

    float* h0bufs[2] = {initbuf, h0b};
    float* h1bufs[2] = {initbuf + BATCH * HID, h1b};
    float* abufs[2]  = {a0, a1};

    for (int t = 0; t < HOR; t++) {
        int cur = t & 1, nxt = 1 - cur;
        k_gru0_mma<<<dim3(4, BATCH / 64), 256>>>(abufs[cur], h0bufs[cur],
                                                 Wih0, Whh0, bih0, bhh0, h0bufs[nxt]);
        k_gru1_mma<<<dim3(4, BATCH / 64), 256>>>(h0bufs[nxt], h1bufs[cur],
                                                 Wih1, Whh1, bih1, bhh1, h1bufs[nxt]);
        k_logits<<<BATCH / 32, 256>>>(h1bufs[nxt], Wa, ba, out, abufs[nxt], t);
    }
}

// round 4
// speedup vs baseline: 3.3729x; 1.3598x over previous
#include <cuda_runtime.h>
#include <math.h>
#include <stdint.h>

#define BATCH 32768
#define SDIM 512
#define HID 256
#define ACT 8
#define HOR 10

// ---------------- scratch (device globals; no allocation) ----------------
__device__ float g_h1[BATCH * HID];
__device__ float g_h2[BATCH * HID];
__device__ float g_init[BATCH * 2 * HID];
__device__ float g_h0b[BATCH * HID];
__device__ float g_h1b[BATCH * HID];
__device__ float g_a0[BATCH * ACT];
__device__ float g_a1[BATCH * ACT];

// packed tf32 fragment-ordered weights
__device__ uint32_t g_W1p[256 * 1024];
__device__ uint32_t g_W2p[256 * 256];
__device__ uint32_t g_Winitp[512 * 256];
__device__ uint32_t g_Wih1p[768 * 256];
__device__ uint32_t g_Whh1p[768 * 256];
__device__ uint32_t g_Whh0p[768 * 256];
__device__ uint32_t g_Wih0p[768 * 8];

// ---------------- helpers ----------------
__device__ __forceinline__ uint32_t f2tf(float f) {
    uint32_t u;
    asm("cvt.rna.tf32.f32 %0, %1;" : "=r"(u) : "f"(f));
    return u;
}

__device__ __forceinline__ void mma8(float c[4], const uint32_t a[4],
                                     uint32_t b0, uint32_t b1) {
    asm volatile(
        "mma.sync.aligned.m16n8k8.row.col.f32.tf32.tf32.f32 "
        "{%0,%1,%2,%3}, {%4,%5,%6,%7}, {%8,%9}, {%0,%1,%2,%3};"
        : "+f"(c[0]), "+f"(c[1]), "+f"(c[2]), "+f"(c[3])
        : "r"(a[0]), "r"(a[1]), "r"(a[2]), "r"(a[3]), "r"(b0), "r"(b1));
}

__device__ __forceinline__ float sigm(float x) {
    return 1.0f / (1.0f + expf(-x));
}

// fragment load: Wp layout [nb][kb][lane][4]; offset = ((nb*KB+kb)*32+lane)*4
__device__ __forceinline__ uint4 ldfrag(const uint32_t* __restrict__ Wp,
                                        int nb, int kb, int KB, int lane) {
    return *(const uint4*)&Wp[((nb * KB + kb) * 32 + lane) * 4];
}

// ---------------- pack kernels ----------------
// W[N][K] row-major -> Wp: per (nb,kb) 32 lanes x 4 regs:
//   lane l, reg q -> W[nb*8 + (l>>2)][kb*16 + q*4 + (l&3)]
__global__ void k_pack(const float* __restrict__ W, uint32_t* __restrict__ Wp,
                       int N, int K) {
    int i = blockIdx.x * blockDim.x + threadIdx.x;
    if (i >= N * K) return;
    int KB = K >> 4;
    int q = i & 3;
    int lane = (i >> 2) & 31;
    int t = i >> 7;
    int kb = t % KB, nb = t / KB;
    int col = nb * 8 + (lane >> 2);
    int k = kb * 16 + q * 4 + (lane & 3);
    Wp[i] = f2tf(W[col * K + k]);
}

// K=8 variant: per nb 32 lanes x 2 regs: lane l, reg q -> W[nb*8+(l>>2)][q*4+(l&3)]
__global__ void k_pack8(const float* __restrict__ W, uint32_t* __restrict__ Wp, int N) {
    int i = blockIdx.x * blockDim.x + threadIdx.x;
    if (i >= N * 8) return;
    int q = i & 1;
    int lane = (i >> 1) & 31;
    int nb = i >> 6;
    int col = nb * 8 + (lane >> 2);
    int k = q * 4 + (lane & 3);
    Wp[i] = f2tf(W[col * 8 + k]);
}

// ---------------- zero kernel ----------------
__global__ void k_zero(float* __restrict__ p, int n) {
    int i = blockIdx.x * blockDim.x + threadIdx.x;
    if (i < n) p[i] = 0.0f;
}

// ---------------- fc1 (tf32 MMA, direct-B) + LayerNorm + ReLU ----------------
// BM=32, BN=256, K=1024; 8 warps: wm(2) x wn(4), nt=8
__global__ __launch_bounds__(256) void k_fc1_mma(
    const float* __restrict__ s0, const float* __restrict__ s1,
    const uint32_t* __restrict__ W1p, const float* __restrict__ b1,
    const float* __restrict__ gam, const float* __restrict__ bet,
    float* __restrict__ out)
{
    __shared__ __align__(16) uint32_t SB[8448];   // Xs[32][20] then epilogue Cs[32][264]

    const int tid  = threadIdx.x;
    const int rowBase = blockIdx.x * 32;
    const int warp = tid >> 5, lane = tid & 31;
    const int wm = warp >> 2, wn = warp & 3;
    const int g  = lane >> 2, t4 = lane & 3;

    float acc[8][4];
#pragma unroll
    for (int i = 0; i < 8; i++)
#pragma unroll
        for (int j = 0; j < 4; j++) acc[i][j] = 0.0f;

    for (int k0 = 0; k0 < 1024; k0 += 16) {
        if (tid < 128) {
            int r = tid >> 2, lk = (tid & 3) * 4;
            int k = k0 + lk;
            float4 v;
            if (k < 512) v = *(const float4*)&s0[(rowBase + r) * 512 + k];
            else         v = *(const float4*)&s1[(rowBase + r) * 512 + (k - 512)];
            uint32_t* Xp = &SB[r * 20 + lk];
            Xp[0] = f2tf(v.x); Xp[1] = f2tf(v.y); Xp[2] = f2tf(v.z); Xp[3] = f2tf(v.w);
        }
        __syncthreads();
        uint32_t a[2][4];
#pragma unroll
        for (int ks = 0; ks < 2; ks++) {
            a[ks][0] = SB[(wm * 16 + g) * 20 + ks * 8 + t4];
            a[ks][1] = SB[(wm * 16 + g + 8) * 20 + ks * 8 + t4];
            a[ks][2] = SB[(wm * 16 + g) * 20 + ks * 8 + t4 + 4];
            a[ks][3] = SB[(wm * 16 + g + 8) * 20 + ks * 8 + t4 + 4];
        }
        int kb = k0 >> 4;
#pragma unroll
        for (int nt = 0; nt < 8; nt++) {
            uint4 b = ldfrag(W1p, wn * 8 + nt, kb, 64, lane);
            mma8(acc[nt], a[0], b.x, b.y);
            mma8(acc[nt], a[1], b.z, b.w);
        }
        __syncthreads();
    }

    float* Cs = (float*)SB;
#pragma unroll
    for (int nt = 0; nt < 8; nt++)
#pragma unroll
        for (int rix = 0; rix < 4; rix++) {
            int row = wm * 16 + g + 8 * (rix >> 1);
            int col = wn * 64 + nt * 8 + t4 * 2 + (rix & 1);
            Cs[row * 264 + col] = acc[nt][rix];
        }
    __syncthreads();

    for (int rr = 0; rr < 4; rr++) {
        int row = warp * 4 + rr;
        float v[8];
        float sum = 0.0f, sq = 0.0f;
#pragma unroll
        for (int i = 0; i < 8; i++) {
            int c = lane + 32 * i;
            v[i] = Cs[row * 264 + c] + b1[c];
            sum += v[i];
            sq  += v[i] * v[i];
        }
#pragma unroll
        for (int o = 16; o; o >>= 1) {
            sum += __shfl_xor_sync(0xffffffffu, sum, o);
            sq  += __shfl_xor_sync(0xffffffffu, sq, o);
        }
        float mean = sum * (1.0f / 256.0f);
        float var  = sq * (1.0f / 256.0f) - mean * mean;
        float rstd = rsqrtf(var + 1e-5f);
#pragma unroll
        for (int i = 0; i < 8; i++) {
            int c = lane + 32 * i;
            float o = (v[i] - mean) * rstd * gam[c] + bet[c];
            out[(rowBase + row) * 256 + c] = fmaxf(o, 0.0f);
        }
    }
}

// ---------------- generic GEMM (direct-B): C[M,N] = X[M,256] @ W[N,256].T + b ----------------
// BM=64, BN=64, 8 warps: wm(4) x wn(2), nt=4
template <int RELU>
__global__ __launch_bounds__(256) void k_gemm_mma(
    const float* __restrict__ X, const uint32_t* __restrict__ Wp,
    const float* __restrict__ b, float* __restrict__ C, int N)
{
    __shared__ __align__(16) uint32_t Xs[64][20];

    const int tid = threadIdx.x;
    const int m0 = blockIdx.y * 64, n0 = blockIdx.x * 64;
    const int warp = tid >> 5, lane = tid & 31;
    const int wm = warp >> 1, wn = warp & 1;
    const int g = lane >> 2, t4 = lane & 3;
    const int lr = tid >> 2, lk = (tid & 3) * 4;

    float acc[4][4];
#pragma unroll
    for (int i = 0; i < 4; i++)
#pragma unroll
        for (int j = 0; j < 4; j++) acc[i][j] = 0.0f;

    for (int k0 = 0; k0 < 256; k0 += 16) {
        float4 xv = *(const float4*)&X[(m0 + lr) * 256 + k0 + lk];
        Xs[lr][lk + 0] = f2tf(xv.x); Xs[lr][lk + 1] = f2tf(xv.y);
        Xs[lr][lk + 2] = f2tf(xv.z); Xs[lr][lk + 3] = f2tf(xv.w);
        __syncthreads();
        uint32_t a[2][4];
#pragma unroll
        for (int ks = 0; ks < 2; ks++) {
            a[ks][0] = Xs[wm * 16 + g][ks * 8 + t4];
            a[ks][1] = Xs[wm * 16 + g + 8][ks * 8 + t4];
            a[ks][2] = Xs[wm * 16 + g][ks * 8 + t4 + 4];
            a[ks][3] = Xs[wm * 16 + g + 8][ks * 8 + t4 + 4];
        }
        int kb = k0 >> 4;
#pragma unroll
        for (int nt = 0; nt < 4; nt++) {
            uint4 bw = ldfrag(Wp, (n0 >> 3) + wn * 4 + nt, kb, 16, lane);
            mma8(acc[nt], a[0], bw.x, bw.y);
            mma8(acc[nt], a[1], bw.z, bw.w);
        }
        __syncthreads();
    }

#pragma unroll
    for (int nt = 0; nt < 4; nt++)
#pragma unroll
        for (int rix = 0; rix < 4; rix++) {
            int row = m0 + wm * 16 + g + 8 * (rix >> 1);
            int col = n0 + wn * 32 + nt * 8 + t4 * 2 + (rix & 1);
            float v = acc[nt][rix] + b[col];
            if (RELU) v = fmaxf(v, 0.0f);
            C[row * N + col] = v;
        }
}

// ---------------- GRU cell 1 (direct-B, warp=32x16) ----------------
// BM=64 (wm 2 x 32 rows), BN=64 (wn 4 x 16 cols, nt=2)
__global__ __launch_bounds__(256) void k_gru1_mma(
    const float* __restrict__ x_in, const float* __restrict__ h_in,
    const uint32_t* __restrict__ Wihp, const uint32_t* __restrict__ Whhp,
    const float* __restrict__ bih, const float* __restrict__ bhh,
    float* __restrict__ h_out)
{
    __shared__ __align__(16) uint32_t Xs[64][20];
    __shared__ __align__(16) uint32_t Hs[64][20];

    const int tid = threadIdx.x;
    const int m0 = blockIdx.y * 64, c0b = blockIdx.x * 64;
    const int warp = tid >> 5, lane = tid & 31;
    const int wm = warp >> 2, wn = warp & 3;
    const int g = lane >> 2, t4 = lane & 3;
    const int lr = tid >> 2, lk = (tid & 3) * 4;

    float accR[2][2][4], accZ[2][2][4], accIN[2][2][4], accHN[2][2][4];
#pragma unroll
    for (int mf = 0; mf < 2; mf++)
#pragma unroll
        for (int nt = 0; nt < 2; nt++)
#pragma unroll
            for (int j = 0; j < 4; j++) {
                accR[mf][nt][j] = 0.0f; accZ[mf][nt][j] = 0.0f;
                accIN[mf][nt][j] = 0.0f; accHN[mf][nt][j] = 0.0f;
            }

    for (int k0 = 0; k0 < 256; k0 += 16) {
        float4 xv = *(const float4*)&x_in[(m0 + lr) * 256 + k0 + lk];
        float4 hv = *(const float4*)&h_in[(m0 + lr) * 256 + k0 + lk];
        Xs[lr][lk + 0] = f2tf(xv.x); Xs[lr][lk + 1] = f2tf(xv.y);
        Xs[lr][lk + 2] = f2tf(xv.z); Xs[lr][lk + 3] = f2tf(xv.w);
        Hs[lr][lk + 0] = f2tf(hv.x); Hs[lr][lk + 1] = f2tf(hv.y);
        Hs[lr][lk + 2] = f2tf(hv.z); Hs[lr][lk + 3] = f2tf(hv.w);
        __syncthreads();

        uint32_t ax[2][2][4], ah[2][2][4];
#pragma unroll
        for (int mf = 0; mf < 2; mf++) {
            int rb = wm * 32 + mf * 16 + g;
#pragma unroll
            for (int ks = 0; ks < 2; ks++) {
                ax[mf][ks][0] = Xs[rb][ks * 8 + t4];
                ax[mf][ks][1] = Xs[rb + 8][ks * 8 + t4];
                ax[mf][ks][2] = Xs[rb][ks * 8 + t4 + 4];
                ax[mf][ks][3] = Xs[rb + 8][ks * 8 + t4 + 4];
                ah[mf][ks][0] = Hs[rb][ks * 8 + t4];
                ah[mf][ks][1] = Hs[rb + 8][ks * 8 + t4];
                ah[mf][ks][2] = Hs[rb][ks * 8 + t4 + 4];
                ah[mf][ks][3] = Hs[rb + 8][ks * 8 + t4 + 4];
            }
        }

        int kb = k0 >> 4;
#pragma unroll
        for (int nt = 0; nt < 2; nt++) {
            int nbB = (c0b + wn * 16 + nt * 8) >> 3;
            uint4 b_ir = ldfrag(Wihp,      nbB, kb, 16, lane);
            uint4 b_iz = ldfrag(Wihp, 32 + nbB, kb, 16, lane);
            uint4 b_in = ldfrag(Wihp, 64 + nbB, kb, 16, lane);
            uint4 b_hr = ldfrag(Whhp,      nbB, kb, 16, lane);
            uint4 b_hz = ldfrag(Whhp, 32 + nbB, kb, 16, lane);
            uint4 b_hn = ldfrag(Whhp, 64 + nbB, kb, 16, lane);
#pragma unroll
            for (int mf = 0; mf < 2; mf++) {
                mma8(accR[mf][nt],  ax[mf][0], b_ir.x, b_ir.y);
                mma8(accR[mf][nt],  ax[mf][1], b_ir.z, b_ir.w);
                mma8(accR[mf][nt],  ah[mf][0], b_hr.x, b_hr.y);
                mma8(accR[mf][nt],  ah[mf][1], b_hr.z, b_hr.w);
                mma8(accZ[mf][nt],  ax[mf][0], b_iz.x, b_iz.y);
                mma8(accZ[mf][nt],  ax[mf][1], b_iz.z, b_iz.w);
                mma8(accZ[mf][nt],  ah[mf][0], b_hz.x, b_hz.y);
                mma8(accZ[mf][nt],  ah[mf][1], b_hz.z, b_hz.w);
                mma8(accIN[mf][nt], ax[mf][0], b_in.x, b_in.y);
                mma8(accIN[mf][nt], ax[mf][1], b_in.z, b_in.w);
                mma8(accHN[mf][nt], ah[mf][0], b_hn.x, b_hn.y);
                mma8(accHN[mf][nt], ah[mf][1], b_hn.z, b_hn.w);
            }
        }
        __syncthreads();
    }

#pragma unroll
    for (int mf = 0; mf < 2; mf++)
#pragma unroll
        for (int nt = 0; nt < 2; nt++)
#pragma unroll
            for (int rix = 0; rix < 4; rix++) {
                int row = m0 + wm * 32 + mf * 16 + g + 8 * (rix >> 1);
                int col = c0b + wn * 16 + nt * 8 + t4 * 2 + (rix & 1);
                float r = sigm(accR[mf][nt][rix] + bih[col] + bhh[col]);
                float z = sigm(accZ[mf][nt][rix] + bih[col + 256] + bhh[col + 256]);
                float n = tanhf(accIN[mf][nt][rix] + bih[col + 512] +
                                r * (accHN[mf][nt][rix] + bhh[col + 512]));
                float hold = h_in[row * 256 + col];
                h_out[row * 256 + col] = (1.0f - z) * n + z * hold;
            }
}

// ---------------- GRU cell 0 (direct-B, warp=32x16): x=a [B,8], h [B,256] ----------------
__global__ __launch_bounds__(256) void k_gru0_mma(
    const float* __restrict__ a_in, const float* __restrict__ h_in,
    const uint32_t* __restrict__ Wih0p, const uint32_t* __restrict__ Whhp,
    const float* __restrict__ bih, const float* __restrict__ bhh,
    float* __restrict__ h_out)
{
    __shared__ __align__(16) uint32_t Hs[64][20];
    __shared__ __align__(16) uint32_t As[64][12];

    const int tid = threadIdx.x;
    const int m0 = blockIdx.y * 64, c0b = blockIdx.x * 64;
    const int warp = tid >> 5, lane = tid & 31;
    const int wm = warp >> 2, wn = warp & 3;
    const int g = lane >> 2, t4 = lane & 3;
    const int lr = tid >> 2, lk = (tid & 3) * 4;

    float accR[2][2][4], accZ[2][2][4], accIN[2][2][4], accHN[2][2][4];
#pragma unroll
    for (int mf = 0; mf < 2; mf++)
#pragma unroll
        for (int nt = 0; nt < 2; nt++)
#pragma unroll
            for (int j = 0; j < 4; j++) {
                accR[mf][nt][j] = 0.0f; accZ[mf][nt][j] = 0.0f;
                accIN[mf][nt][j] = 0.0f; accHN[mf][nt][j] = 0.0f;
            }

    // x path (K=8)
    {
        int r = tid >> 2, k2 = (tid & 3) * 2;
        float2 av = *(const float2*)&a_in[(m0 + r) * 8 + k2];
        As[r][k2] = f2tf(av.x); As[r][k2 + 1] = f2tf(av.y);
    }
    __syncthreads();
    {
        uint32_t a[2][4];
#pragma unroll
        for (int mf = 0; mf < 2; mf++) {
            int rb = wm * 32 + mf * 16 + g;
            a[mf][0] = As[rb][t4];
            a[mf][1] = As[rb + 8][t4];
            a[mf][2] = As[rb][t4 + 4];
            a[mf][3] = As[rb + 8][t4 + 4];
        }
#pragma unroll
        for (int nt = 0; nt < 2; nt++) {
            int nbB = (c0b + wn * 16 + nt * 8) >> 3;
            uint2 b_ir = *(const uint2*)&Wih0p[((     nbB) * 32 + lane) * 2];
            uint2 b_iz = *(const uint2*)&Wih0p[((32 + nbB) * 32 + lane) * 2];
            uint2 b_in = *(const uint2*)&Wih0p[((64 + nbB) * 32 + lane) * 2];
#pragma unroll
            for (int mf = 0; mf < 2; mf++) {
                mma8(accR[mf][nt],  a[mf], b_ir.x, b_ir.y);
                mma8(accZ[mf][nt],  a[mf], b_iz.x, b_iz.y);
                mma8(accIN[mf][nt], a[mf], b_in.x, b_in.y);
            }
        }
    }
    __syncthreads();

    // h path (K=256)
    for (int k0 = 0; k0 < 256; k0 += 16) {
        float4 hv = *(const float4*)&h_in[(m0 + lr) * 256 + k0 + lk];
        Hs[lr][lk + 0] = f2tf(hv.x); Hs[lr][lk + 1] = f2tf(hv.y);
        Hs[lr][lk + 2] = f2tf(hv.z); Hs[lr][lk + 3] = f2tf(hv.w);
        __syncthreads();

        uint32_t ah[2][2][4];
#pragma unroll
        for (int mf = 0; mf < 2; mf++) {
            int rb = wm * 32 + mf * 16 + g;
#pragma unroll
            for (int ks = 0; ks < 2; ks++) {
                ah[mf][ks][0] = Hs[rb][ks * 8 + t4];
                ah[mf][ks][1] = Hs[rb + 8][ks * 8 + t4];
                ah[mf][ks][2] = Hs[rb][ks * 8 + t4 + 4];
                ah[mf][ks][3] = Hs[rb + 8][ks * 8 + t4 + 4];
            }
        }

        int kb = k0 >> 4;
#pragma unroll
        for (int nt = 0; nt < 2; nt++) {
            int nbB = (c0b + wn * 16 + nt * 8) >> 3;
            uint4 b_hr = ldfrag(Whhp,      nbB, kb, 16, lane);
            uint4 b_hz = ldfrag(Whhp, 32 + nbB, kb, 16, lane);
            uint4 b_hn = ldfrag(Whhp, 64 + nbB, kb, 16, lane);
#pragma unroll
            for (int mf = 0; mf < 2; mf++) {
                mma8(accR[mf][nt],  ah[mf][0], b_hr.x, b_hr.y);
                mma8(accR[mf][nt],  ah[mf][1], b_hr.z, b_hr.w);
                mma8(accZ[mf][nt],  ah[mf][0], b_hz.x, b_hz.y);
                mma8(accZ[mf][nt],  ah[mf][1], b_hz.z, b_hz.w);
                mma8(accHN[mf][nt], ah[mf][0], b_hn.x, b_hn.y);
                mma8(accHN[mf][nt], ah[mf][1], b_hn.z, b_hn.w);
            }
        }
        __syncthreads();
    }

#pragma unroll
    for (int mf = 0; mf < 2; mf++)
#pragma unroll
        for (int nt = 0; nt < 2; nt++)
#pragma unroll
            for (int rix = 0; rix < 4; rix++) {
                int row = m0 + wm * 32 + mf * 16 + g + 8 * (rix >> 1);
                int col = c0b + wn * 16 + nt * 8 + t4 * 2 + (rix & 1);
                float r = sigm(accR[mf][nt][rix] + bih[col] + bhh[col]);
                float z = sigm(accZ[mf][nt][rix] + bih[col + 256] + bhh[col + 256]);
                float n = tanhf(accIN[mf][nt][rix] + bih[col + 512] +
                                r * (accHN[mf][nt][rix] + bhh[col + 512]));
                float hold = h_in[row * 256 + col];
                h_out[row * 256 + col] = (1.0f - z) * n + z * hold;
            }
}

// ---------------- logits + softmax ----------------
__global__ __launch_bounds__(256) void k_logits(
    const float* __restrict__ h, const float* __restrict__ Wa,
    const float* __restrict__ ba, float* __restrict__ out,
    float* __restrict__ a_next, int t)
{
    __shared__ float hs[32][257];
    __shared__ float Was[8][257];

    const int tid = threadIdx.x;
    const int rb0 = blockIdx.x * 32;

#pragma unroll
    for (int i = 0; i < 8; i++) {
        int idx = i * 256 + tid;
        int j = idx >> 8, k = idx & 255;
        Was[j][k] = Wa[j * 256 + k];
    }
#pragma unroll
    for (int i = 0; i < 32; i++) {
        int idx = i * 256 + tid;
        int r = idx >> 8, k = idx & 255;
        hs[r][k] = h[(rb0 + r) * 256 + k];
    }
    __syncthreads();

    const int r = tid >> 3, j = tid & 7;
    float s0 = 0.0f, s1 = 0.0f, s2 = 0.0f, s3 = 0.0f;
#pragma unroll 8
    for (int k = 0; k < 256; k += 4) {
        s0 += hs[r][k + 0] * Was[j][k + 0];
        s1 += hs[r][k + 1] * Was[j][k + 1];
        s2 += hs[r][k + 2] * Was[j][k + 2];
        s3 += hs[r][k + 3] * Was[j][k + 3];
    }
    float acc = (s0 + s1) + (s2 + s3) + ba[j];

    out[(rb0 + r) * (HOR * ACT) + t * ACT + j] = acc;

    float m = acc;
#pragma unroll
    for (int o = 4; o; o >>= 1) m = fmaxf(m, __shfl_xor_sync(0xffffffffu, m, o));
    float e = expf(acc - m);
    float s = e;
#pragma unroll
    for (int o = 4; o; o >>= 1) s += __shfl_xor_sync(0xffffffffu, s, o);
    a_next[(rb0 + r) * ACT + j] = e / s;
}

// ---------------- host ----------------
extern "C" void kernel_launch(void* const* d_in, const int* in_sizes, int n_in,
                              void* d_out, int out_size)
{
    const float* s0    = (const float*)d_in[0];
    const float* s1    = (const float*)d_in[1];
    const float* W1    = (const float*)d_in[3];
    const float* b1    = (const float*)d_in[4];
    const float* lng   = (const float*)d_in[5];
    const float* lnb   = (const float*)d_in[6];
    const float* W2    = (const float*)d_in[7];
    const float* b2    = (const float*)d_in[8];
    const float* Wih0  = (const float*)d_in[9];
    const float* Whh0  = (const float*)d_in[10];
    const float* bih0  = (const float*)d_in[11];
    const float* bhh0  = (const float*)d_in[12];
    const float* Wih1  = (const float*)d_in[13];
    const float* Whh1  = (const float*)d_in[14];
    const float* bih1  = (const float*)d_in[15];
    const float* bhh1  = (const float*)d_in[16];
    const float* Wa    = (const float*)d_in[17];
    const float* ba    = (const float*)d_in[18];
    const float* Winit = (const float*)d_in[19];
    const float* binit = (const float*)d_in[20];
    float* out = (float*)d_out;

    float *h1buf, *h2buf, *initbuf, *h0b, *h1b, *a0, *a1;
    uint32_t *W1p, *W2p, *Winitp, *Wih1p, *Whh1p, *Whh0p, *Wih0p;
    cudaGetSymbolAddress((void**)&h1buf, g_h1);
    cudaGetSymbolAddress((void**)&h2buf, g_h2);
    cudaGetSymbolAddress((void**)&initbuf, g_init);
    cudaGetSymbolAddress((void**)&h0b, g_h0b);
    cudaGetSymbolAddress((void**)&h1b, g_h1b);
    cudaGetSymbolAddress((void**)&a0, g_a0);
    cudaGetSymbolAddress((void**)&a1, g_a1);
    cudaGetSymbolAddress((void**)&W1p, g_W1p);
    cudaGetSymbolAddress((void**)&W2p, g_W2p);
    cudaGetSymbolAddress((void**)&Winitp, g_Winitp);
    cudaGetSymbolAddress((void**)&Wih1p, g_Wih1p);
    cudaGetSymbolAddress((void**)&Whh1p, g_Whh1p);
    cudaGetSymbolAddress((void**)&Whh0p, g_Whh0p);
    cudaGetSymbolAddress((void**)&Wih0p, g_Wih0p);

    k_zero<<<(BATCH * ACT + 255) / 256, 256>>>(a0, BATCH * ACT);

    // pack weights (tf32, fragment order)
    k_pack<<<(256 * 1024 + 255) / 256, 256>>>(W1, W1p, 256, 1024);
    k_pack<<<(256 * 256 + 255) / 256, 256>>>(W2, W2p, 256, 256);
    k_pack<<<(512 * 256 + 255) / 256, 256>>>(Winit, Winitp, 512, 256);
    k_pack<<<(768 * 256 + 255) / 256, 256>>>(Wih1, Wih1p, 768, 256);
    k_pack<<<(768 * 256 + 255) / 256, 256>>>(Whh1, Whh1p, 768, 256);
    k_pack<<<(768 * 256 + 255) / 256, 256>>>(Whh0, Whh0p, 768, 256);
    k_pack8<<<(768 * 8 + 255) / 256, 256>>>(Wih0, Wih0p, 768);

    // prologue MLP
    k_fc1_mma<<<BATCH / 32, 256>>>(s0, s1, W1p, b1, lng, lnb, h1buf);
    k_gemm_mma<1><<<dim3(4, BATCH / 64), 256>>>(h1buf, W2p, b2, h2buf, 256);
    k_gemm_mma<0><<<dim3(8, BATCH / 64), 256>>>(h2buf, Winitp, binit, initbuf, 512);

    float* h0bufs[2] = {initbuf, h0b};
    float* h1bufs[2] = {initbuf + BATCH * HID, h1b};
    float* abufs[2]  = {a0, a1};

    for (int t = 0; t < HOR; t++) {
        int cur = t & 1, nxt = 1 - cur;
        k_gru0_mma<<<dim3(4, BATCH / 64), 256>>>(abufs[cur], h0bufs[cur],
                                                 Wih0p, Whh0p, bih0, bhh0, h0bufs[nxt]);
        k_gru1_mma<<<dim3(4, BATCH / 64), 256>>>(h0bufs[nxt], h1bufs[cur],
                                                 Wih1p, Whh1p, bih1, bhh1, h1bufs[nxt]);
        k_logits<<<BATCH / 32, 256>>>(h1bufs[nxt], Wa, ba, out, abufs[nxt], t);
    }
}